// round 1
// baseline (speedup 1.0000x reference)
#include <cuda_runtime.h>
#include <math.h>

#define N0    1000000
#define NN1   40960
#define NN2   4096
#define EE1   1024000
#define EE2   40960
#define IN_C  100
#define HID   256
#define OUT_C 47

// ---------------- scratch (device globals; no allocation allowed) ----------------
__device__ int   g_is64;
__device__ int   g_counts1[NN1];
__device__ int   g_offs1[NN1 + 1];
__device__ int   g_cursor1[NN1];
__device__ int   g_bucket1[EE1];
__device__ float g_agg1[(size_t)NN1 * IN_C];
__device__ float g_h[(size_t)NN1 * HID];
__device__ int   g_counts2[NN2];
__device__ int   g_offs2[NN2 + 1];
__device__ int   g_cursor2[NN2];
__device__ int   g_bucket2[EE2];
__device__ float g_agg2[(size_t)NN2 * HID];

__device__ __forceinline__ int loadIdx(const void* p, int i, int is64) {
    return is64 ? (int)((const long long*)p)[i] : ((const int*)p)[i];
}

// ---------------- index dtype probe ----------------
__global__ void k_detect(const void* src1) {
    if (threadIdx.x == 0) {
        const uint2* q = (const uint2*)src1;   // if int64: .y (high word) == 0 always
        int is64 = 1;
        for (int i = 0; i < 64; i++) {
            if (q[i].y != 0u) { is64 = 0; break; }
        }
        g_is64 = is64;
    }
}

__global__ void k_zero() {
    int i = blockIdx.x * blockDim.x + threadIdx.x;
    if (i < NN1) g_counts1[i] = 0;
    if (i < NN2) g_counts2[i] = 0;
}

// ---------------- CSR build: count / scan / scatter ----------------
__global__ void k_count1(const void* dst) {
    int i = blockIdx.x * blockDim.x + threadIdx.x;
    if (i < EE1) atomicAdd(&g_counts1[loadIdx(dst, i, g_is64)], 1);
}
__global__ void k_count2(const void* dst) {
    int i = blockIdx.x * blockDim.x + threadIdx.x;
    if (i < EE2) atomicAdd(&g_counts2[loadIdx(dst, i, g_is64)], 1);
}

__global__ void k_scan() {   // grid=2, block=1024; block 0 -> layer1, block 1 -> layer2
    int which = blockIdx.x;
    int n      = (which == 0) ? NN1 : NN2;
    int* counts = (which == 0) ? g_counts1 : g_counts2;
    int* offs   = (which == 0) ? g_offs1   : g_offs2;
    int* cursor = (which == 0) ? g_cursor1 : g_cursor2;

    __shared__ int s[1024];
    __shared__ int carry;
    int tid = threadIdx.x;
    if (tid == 0) carry = 0;
    __syncthreads();

    for (int base = 0; base < n; base += 1024) {
        int v = (base + tid < n) ? counts[base + tid] : 0;
        s[tid] = v;
        __syncthreads();
        #pragma unroll
        for (int off = 1; off < 1024; off <<= 1) {
            int t = (tid >= off) ? s[tid - off] : 0;
            __syncthreads();
            s[tid] += t;
            __syncthreads();
        }
        int excl = s[tid] - v + carry;
        if (base + tid < n) { offs[base + tid] = excl; cursor[base + tid] = excl; }
        __syncthreads();
        if (tid == 0) carry += s[1023];
        __syncthreads();
    }
    if (tid == 0) offs[n] = carry;
}

__global__ void k_scatter1(const void* src, const void* dst) {
    int i = blockIdx.x * blockDim.x + threadIdx.x;
    if (i < EE1) {
        int is64 = g_is64;
        int d = loadIdx(dst, i, is64);
        int pos = atomicAdd(&g_cursor1[d], 1);
        g_bucket1[pos] = loadIdx(src, i, is64);
    }
}
__global__ void k_scatter2(const void* src, const void* dst) {
    int i = blockIdx.x * blockDim.x + threadIdx.x;
    if (i < EE2) {
        int is64 = g_is64;
        int d = loadIdx(dst, i, is64);
        int pos = atomicAdd(&g_cursor2[d], 1);
        g_bucket2[pos] = loadIdx(src, i, is64);
    }
}

// ---------------- layer 1 mean-aggregate: warp per dst, 25 x float4 per row ----------------
__global__ void k_agg1(const float* __restrict__ x) {
    int w    = (blockIdx.x * blockDim.x + threadIdx.x) >> 5;
    int lane = threadIdx.x & 31;
    if (w >= NN1) return;
    int beg = g_offs1[w], end = g_offs1[w + 1];

    float4 acc = make_float4(0.f, 0.f, 0.f, 0.f);
    int i = beg;
    for (; i + 1 < end; i += 2) {
        int s0 = g_bucket1[i], s1 = g_bucket1[i + 1];
        if (lane < 25) {
            float4 v0 = ((const float4*)(x + (size_t)s0 * IN_C))[lane];
            float4 v1 = ((const float4*)(x + (size_t)s1 * IN_C))[lane];
            acc.x += v0.x + v1.x; acc.y += v0.y + v1.y;
            acc.z += v0.z + v1.z; acc.w += v0.w + v1.w;
        }
    }
    if (i < end) {
        int s0 = g_bucket1[i];
        if (lane < 25) {
            float4 v0 = ((const float4*)(x + (size_t)s0 * IN_C))[lane];
            acc.x += v0.x; acc.y += v0.y; acc.z += v0.z; acc.w += v0.w;
        }
    }
    int cnt = end - beg;
    float inv = 1.0f / (float)(cnt > 1 ? cnt : 1);
    if (lane < 25) {
        float4 o = make_float4(acc.x * inv, acc.y * inv, acc.z * inv, acc.w * inv);
        ((float4*)(g_agg1 + (size_t)w * IN_C))[lane] = o;
    }
}

// ---------------- GEMM1 fused: h = relu([agg1 | x_dst] @ [W1l; W1r] + b1) ----------------
// M=40960, K=200 (virtual concat), N=256. BM=BN=128, BK=8, 256 threads, 8x8 per thread.
__global__ void __launch_bounds__(256) k_gemm1(const float* __restrict__ x,
                                               const float* __restrict__ W1l,
                                               const float* __restrict__ W1r,
                                               const float* __restrict__ b1l) {
    __shared__ float As[8][128];
    __shared__ float Bs[8][128];

    int tid = threadIdx.x;
    int tm = (tid >> 4) * 8;        // 0..120
    int tn = (tid & 15) * 8;        // 0..120
    int mbase = blockIdx.y * 128;
    int nbase = blockIdx.x * 128;

    float acc[8][8];
    #pragma unroll
    for (int i = 0; i < 8; i++)
        #pragma unroll
        for (int j = 0; j < 8; j++) acc[i][j] = 0.f;

    int a_row  = tid >> 1;          // 0..127
    int a_col4 = (tid & 1) * 4;     // 0 or 4
    int b_k    = tid >> 5;          // 0..7
    int b_n4   = (tid & 31) * 4;    // 0..124

    for (int t = 0; t < 25; t++) {          // K=200 = 25*8
        int k0 = t * 8;
        // load A tile (virtual concat agg1 | x)
        {
            int m_g = mbase + a_row;
            int kc  = k0 + a_col4;
            const float* src = (kc < IN_C)
                ? (g_agg1 + (size_t)m_g * IN_C + kc)
                : (x + (size_t)m_g * IN_C + (kc - IN_C));
            float4 v = *(const float4*)src;
            As[a_col4 + 0][a_row] = v.x;
            As[a_col4 + 1][a_row] = v.y;
            As[a_col4 + 2][a_row] = v.z;
            As[a_col4 + 3][a_row] = v.w;
        }
        // load B tile (virtual concat W1l ; W1r)
        {
            int kg = k0 + b_k;
            const float* src = (kg < IN_C)
                ? (W1l + (size_t)kg * HID + nbase + b_n4)
                : (W1r + (size_t)(kg - IN_C) * HID + nbase + b_n4);
            *(float4*)&Bs[b_k][b_n4] = *(const float4*)src;
        }
        __syncthreads();

        #pragma unroll
        for (int kk = 0; kk < 8; kk++) {
            float a[8], b[8];
            *(float4*)(a)     = *(const float4*)&As[kk][tm];
            *(float4*)(a + 4) = *(const float4*)&As[kk][tm + 4];
            *(float4*)(b)     = *(const float4*)&Bs[kk][tn];
            *(float4*)(b + 4) = *(const float4*)&Bs[kk][tn + 4];
            #pragma unroll
            for (int i = 0; i < 8; i++)
                #pragma unroll
                for (int j = 0; j < 8; j++)
                    acc[i][j] += a[i] * b[j];
        }
        __syncthreads();
    }

    float bb[8];
    #pragma unroll
    for (int j = 0; j < 8; j++) bb[j] = b1l[nbase + tn + j];

    #pragma unroll
    for (int i = 0; i < 8; i++) {
        size_t row = (size_t)(mbase + tm + i);
        float4 o0, o1;
        o0.x = fmaxf(acc[i][0] + bb[0], 0.f);
        o0.y = fmaxf(acc[i][1] + bb[1], 0.f);
        o0.z = fmaxf(acc[i][2] + bb[2], 0.f);
        o0.w = fmaxf(acc[i][3] + bb[3], 0.f);
        o1.x = fmaxf(acc[i][4] + bb[4], 0.f);
        o1.y = fmaxf(acc[i][5] + bb[5], 0.f);
        o1.z = fmaxf(acc[i][6] + bb[6], 0.f);
        o1.w = fmaxf(acc[i][7] + bb[7], 0.f);
        *(float4*)&g_h[row * HID + nbase + tn]     = o0;
        *(float4*)&g_h[row * HID + nbase + tn + 4] = o1;
    }
}

// ---------------- layer 2 mean-aggregate: warp per dst, 64 x float4 per row ----------------
__global__ void k_agg2() {
    int w    = (blockIdx.x * blockDim.x + threadIdx.x) >> 5;
    int lane = threadIdx.x & 31;
    if (w >= NN2) return;
    int beg = g_offs2[w], end = g_offs2[w + 1];

    float4 a0 = make_float4(0.f, 0.f, 0.f, 0.f);
    float4 a1 = make_float4(0.f, 0.f, 0.f, 0.f);
    for (int i = beg; i < end; i++) {
        int s = g_bucket2[i];
        const float4* r = (const float4*)(g_h + (size_t)s * HID);
        float4 v0 = r[lane];
        float4 v1 = r[lane + 32];
        a0.x += v0.x; a0.y += v0.y; a0.z += v0.z; a0.w += v0.w;
        a1.x += v1.x; a1.y += v1.y; a1.z += v1.z; a1.w += v1.w;
    }
    int cnt = end - beg;
    float inv = 1.0f / (float)(cnt > 1 ? cnt : 1);
    float4* o = (float4*)(g_agg2 + (size_t)w * HID);
    o[lane]      = make_float4(a0.x * inv, a0.y * inv, a0.z * inv, a0.w * inv);
    o[lane + 32] = make_float4(a1.x * inv, a1.y * inv, a1.z * inv, a1.w * inv);
}

// ---------------- final: out = log_softmax(agg2@W2l + b2 + h_dst@W2r) ----------------
// warp per row; 2 outputs per lane (47 <= 64)
__global__ void __launch_bounds__(256) k_final(const float* __restrict__ W2l,
                                               const float* __restrict__ b2l,
                                               const float* __restrict__ W2r,
                                               float* __restrict__ out) {
    __shared__ float abuf[8][512];
    int w    = threadIdx.x >> 5;
    int lane = threadIdx.x & 31;
    int r    = blockIdx.x * 8 + w;      // grid = 512 -> rows 0..4095

    float* a = abuf[w];
    const float* agg = g_agg2 + (size_t)r * HID;
    const float* hd  = g_h    + (size_t)r * HID;
    #pragma unroll
    for (int j = 0; j < 8; j++) {
        a[lane + 32 * j]       = agg[lane + 32 * j];
        a[256 + lane + 32 * j] = hd[lane + 32 * j];
    }
    __syncwarp();

    int o1 = lane;           // always < 47
    int o2 = lane + 32;      // valid for lanes 0..14
    bool v2 = (o2 < OUT_C);
    float acc1 = b2l[o1];
    float acc2 = v2 ? b2l[o2] : 0.f;

    #pragma unroll 4
    for (int k = 0; k < HID; k++) {
        float av = a[k];
        const float* Bk = W2l + (size_t)k * OUT_C;
        acc1 += av * Bk[o1];
        if (v2) acc2 += av * Bk[o2];
    }
    #pragma unroll 4
    for (int k = 0; k < HID; k++) {
        float av = a[256 + k];
        const float* Bk = W2r + (size_t)k * OUT_C;
        acc1 += av * Bk[o1];
        if (v2) acc2 += av * Bk[o2];
    }

    float m = v2 ? fmaxf(acc1, acc2) : acc1;
    #pragma unroll
    for (int s = 16; s; s >>= 1) m = fmaxf(m, __shfl_xor_sync(0xffffffffu, m, s));
    float e = expf(acc1 - m) + (v2 ? expf(acc2 - m) : 0.f);
    #pragma unroll
    for (int s = 16; s; s >>= 1) e += __shfl_xor_sync(0xffffffffu, e, s);
    float ls = logf(e);

    out[(size_t)r * OUT_C + o1] = acc1 - m - ls;
    if (v2) out[(size_t)r * OUT_C + o2] = acc2 - m - ls;
}

// ---------------- launch ----------------
extern "C" void kernel_launch(void* const* d_in, const int* in_sizes, int n_in,
                              void* d_out, int out_size) {
    const float* x   = (const float*)d_in[0];
    const float* W1l = (const float*)d_in[1];
    const float* b1l = (const float*)d_in[2];
    const float* W1r = (const float*)d_in[3];
    const float* W2l = (const float*)d_in[4];
    const float* b2l = (const float*)d_in[5];
    const float* W2r = (const float*)d_in[6];
    const void*  src1 = d_in[7];
    const void*  dst1 = d_in[8];
    const void*  src2 = d_in[9];
    const void*  dst2 = d_in[10];
    float* out = (float*)d_out;

    k_detect<<<1, 32>>>(src1);
    k_zero<<<(NN1 + 255) / 256, 256>>>();
    k_count1<<<(EE1 + 255) / 256, 256>>>(dst1);
    k_count2<<<(EE2 + 255) / 256, 256>>>(dst2);
    k_scan<<<2, 1024>>>();
    k_scatter1<<<(EE1 + 255) / 256, 256>>>(src1, dst1);
    k_scatter2<<<(EE2 + 255) / 256, 256>>>(src2, dst2);
    k_agg1<<<NN1 / 8, 256>>>(x);
    k_gemm1<<<dim3(HID / 128, NN1 / 128), 256>>>(x, W1l, W1r, b1l);
    k_agg2<<<NN2 / 8, 256>>>();
    k_final<<<NN2 / 8, 256>>>(W2l, b2l, W2r, out);
}

// round 2
// speedup vs baseline: 1.0194x; 1.0194x over previous
#include <cuda_runtime.h>
#include <math.h>

#define N0    1000000
#define NN1   40960
#define NN2   4096
#define EE1   1024000
#define EE2   40960
#define IN_C  100
#define HID   256
#define OUT_C 47

// ---------------- scratch (device globals; no allocation allowed) ----------------
__device__ int   g_is64;
__device__ int   g_counts1[NN1];
__device__ int   g_offs1[NN1 + 1];
__device__ int   g_cursor1[NN1];
__device__ int   g_bucket1[EE1];
__device__ float g_agg1[(size_t)NN1 * IN_C];
__device__ float g_h[(size_t)NN1 * HID];
__device__ int   g_counts2[NN2];
__device__ int   g_offs2[NN2 + 1];
__device__ int   g_cursor2[NN2];
__device__ int   g_bucket2[EE2];
__device__ float g_agg2[(size_t)NN2 * HID];

__device__ __forceinline__ int loadIdx(const void* p, int i, int is64) {
    return is64 ? (int)((const long long*)p)[i] : ((const int*)p)[i];
}

// ---------------- index dtype probe ----------------
__global__ void k_detect(const void* src1) {
    if (threadIdx.x == 0) {
        const uint2* q = (const uint2*)src1;   // if int64: .y (high word) == 0 always
        int is64 = 1;
        for (int i = 0; i < 64; i++) {
            if (q[i].y != 0u) { is64 = 0; break; }
        }
        g_is64 = is64;
    }
}

__global__ void k_zero() {
    int i = blockIdx.x * blockDim.x + threadIdx.x;
    if (i < NN1) g_counts1[i] = 0;
    if (i < NN2) g_counts2[i] = 0;
}

// ---------------- CSR build: count / scan / scatter (layer1+layer2 merged) ----------------
__global__ void k_count(const void* dst1, const void* dst2) {
    int i = blockIdx.x * blockDim.x + threadIdx.x;
    int is64 = g_is64;
    if (i < EE1) atomicAdd(&g_counts1[loadIdx(dst1, i, is64)], 1);
    if (i < EE2) atomicAdd(&g_counts2[loadIdx(dst2, i, is64)], 1);
}

__global__ void k_scan() {   // grid=2, block=1024; block 0 -> layer1, block 1 -> layer2
    int which = blockIdx.x;
    int n      = (which == 0) ? NN1 : NN2;
    int* counts = (which == 0) ? g_counts1 : g_counts2;
    int* offs   = (which == 0) ? g_offs1   : g_offs2;
    int* cursor = (which == 0) ? g_cursor1 : g_cursor2;

    __shared__ int s[1024];
    __shared__ int carry;
    int tid = threadIdx.x;
    if (tid == 0) carry = 0;
    __syncthreads();

    for (int base = 0; base < n; base += 1024) {
        int v = (base + tid < n) ? counts[base + tid] : 0;
        s[tid] = v;
        __syncthreads();
        #pragma unroll
        for (int off = 1; off < 1024; off <<= 1) {
            int t = (tid >= off) ? s[tid - off] : 0;
            __syncthreads();
            s[tid] += t;
            __syncthreads();
        }
        int excl = s[tid] - v + carry;
        if (base + tid < n) { offs[base + tid] = excl; cursor[base + tid] = excl; }
        __syncthreads();
        if (tid == 0) carry += s[1023];
        __syncthreads();
    }
    if (tid == 0) offs[n] = carry;
}

__global__ void k_scatter(const void* src1, const void* dst1,
                          const void* src2, const void* dst2) {
    int i = blockIdx.x * blockDim.x + threadIdx.x;
    int is64 = g_is64;
    if (i < EE1) {
        int d = loadIdx(dst1, i, is64);
        int pos = atomicAdd(&g_cursor1[d], 1);
        g_bucket1[pos] = loadIdx(src1, i, is64);
    }
    if (i < EE2) {
        int d = loadIdx(dst2, i, is64);
        int pos = atomicAdd(&g_cursor2[d], 1);
        g_bucket2[pos] = loadIdx(src2, i, is64);
    }
}

// ---------------- layer 1 mean-aggregate: warp per dst, 25 x float4 per row ----------------
__global__ void k_agg1(const float* __restrict__ x) {
    int w    = (blockIdx.x * blockDim.x + threadIdx.x) >> 5;
    int lane = threadIdx.x & 31;
    if (w >= NN1) return;
    int beg = g_offs1[w], end = g_offs1[w + 1];

    float4 acc = make_float4(0.f, 0.f, 0.f, 0.f);
    int i = beg;
    for (; i + 1 < end; i += 2) {
        int s0 = g_bucket1[i], s1 = g_bucket1[i + 1];
        if (lane < 25) {
            float4 v0 = ((const float4*)(x + (size_t)s0 * IN_C))[lane];
            float4 v1 = ((const float4*)(x + (size_t)s1 * IN_C))[lane];
            acc.x += v0.x + v1.x; acc.y += v0.y + v1.y;
            acc.z += v0.z + v1.z; acc.w += v0.w + v1.w;
        }
    }
    if (i < end) {
        int s0 = g_bucket1[i];
        if (lane < 25) {
            float4 v0 = ((const float4*)(x + (size_t)s0 * IN_C))[lane];
            acc.x += v0.x; acc.y += v0.y; acc.z += v0.z; acc.w += v0.w;
        }
    }
    int cnt = end - beg;
    float inv = 1.0f / (float)(cnt > 1 ? cnt : 1);
    if (lane < 25) {
        float4 o = make_float4(acc.x * inv, acc.y * inv, acc.z * inv, acc.w * inv);
        ((float4*)(g_agg1 + (size_t)w * IN_C))[lane] = o;
    }
}

// ---------------- GEMM1 fused: h = relu([agg1 | x_dst] @ [W1l; W1r] + b1) ----------------
// M=40960, K=200 (virtual concat), N=256. BM=BN=128, BK=8, 256 threads.
// Packed f32x2 FMA: each thread owns 8m x 8n as 4 m-pairs x 8 n.
// A pairs load directly (m-contiguous); B stored DUPLICATED {b,b} in a
// chunk-swizzled layout [kk][chunk i (0..3)][group g (0..15)] of 16B units so
// the 4 b-loads per kk are lane-consecutive 16B (conflict-free).
__global__ void __launch_bounds__(256) k_gemm1(const float* __restrict__ x,
                                               const float* __restrict__ W1l,
                                               const float* __restrict__ W1r,
                                               const float* __restrict__ b1l) {
    __shared__ float As[8][128];     // [k][m]
    __shared__ float BsD[8 * 256];   // duplicated B, chunk-swizzled

    int tid = threadIdx.x;
    int g   = tid & 15;              // n-group 0..15
    int tm  = (tid >> 4) * 8;        // 0..120
    int tn  = g * 8;                 // 0..120
    int mbase = blockIdx.y * 128;
    int nbase = blockIdx.x * 128;

    unsigned long long acc[4][8];
    #pragma unroll
    for (int mp = 0; mp < 4; mp++)
        #pragma unroll
        for (int n = 0; n < 8; n++) acc[mp][n] = 0ULL;

    int a_row  = tid >> 1;           // 0..127
    int a_col4 = (tid & 1) * 4;      // 0 or 4
    int b_k    = tid >> 5;           // 0..7
    int b_n4   = (tid & 31) * 4;     // 0..124
    int bg     = b_n4 >> 3;          // group 0..15
    int bi0    = (b_n4 & 7) >> 1;    // chunk 0 or 2

    for (int t = 0; t < 25; t++) {   // K=200 = 25*8
        int k0 = t * 8;
        // load A tile (virtual concat agg1 | x), transposed into As[k][m]
        {
            int m_g = mbase + a_row;
            int kc  = k0 + a_col4;
            const float* src = (kc < IN_C)
                ? (g_agg1 + (size_t)m_g * IN_C + kc)
                : (x + (size_t)m_g * IN_C + (kc - IN_C));
            float4 v = *(const float4*)src;
            As[a_col4 + 0][a_row] = v.x;
            As[a_col4 + 1][a_row] = v.y;
            As[a_col4 + 2][a_row] = v.z;
            As[a_col4 + 3][a_row] = v.w;
        }
        // load B tile (virtual concat W1l ; W1r), duplicate into swizzled BsD
        {
            int kg = k0 + b_k;
            const float* src = (kg < IN_C)
                ? (W1l + (size_t)kg * HID + nbase + b_n4)
                : (W1r + (size_t)(kg - IN_C) * HID + nbase + b_n4);
            float4 v = *(const float4*)src;
            float4 c0 = make_float4(v.x, v.x, v.y, v.y);
            float4 c1 = make_float4(v.z, v.z, v.w, v.w);
            *(float4*)&BsD[b_k * 256 + ((bi0    ) * 16 + bg) * 4] = c0;
            *(float4*)&BsD[b_k * 256 + ((bi0 + 1) * 16 + bg) * 4] = c1;
        }
        __syncthreads();

        #pragma unroll
        for (int kk = 0; kk < 8; kk++) {
            ulonglong2 a0 = *(const ulonglong2*)&As[kk][tm];
            ulonglong2 a1 = *(const ulonglong2*)&As[kk][tm + 4];
            unsigned long long ap0 = a0.x, ap1 = a0.y, ap2 = a1.x, ap3 = a1.y;
            #pragma unroll
            for (int i = 0; i < 4; i++) {
                ulonglong2 bb = *(const ulonglong2*)&BsD[kk * 256 + (i * 16 + g) * 4];
                asm("fma.rn.f32x2 %0, %1, %2, %0;" : "+l"(acc[0][2*i  ]) : "l"(ap0), "l"(bb.x));
                asm("fma.rn.f32x2 %0, %1, %2, %0;" : "+l"(acc[1][2*i  ]) : "l"(ap1), "l"(bb.x));
                asm("fma.rn.f32x2 %0, %1, %2, %0;" : "+l"(acc[2][2*i  ]) : "l"(ap2), "l"(bb.x));
                asm("fma.rn.f32x2 %0, %1, %2, %0;" : "+l"(acc[3][2*i  ]) : "l"(ap3), "l"(bb.x));
                asm("fma.rn.f32x2 %0, %1, %2, %0;" : "+l"(acc[0][2*i+1]) : "l"(ap0), "l"(bb.y));
                asm("fma.rn.f32x2 %0, %1, %2, %0;" : "+l"(acc[1][2*i+1]) : "l"(ap1), "l"(bb.y));
                asm("fma.rn.f32x2 %0, %1, %2, %0;" : "+l"(acc[2][2*i+1]) : "l"(ap2), "l"(bb.y));
                asm("fma.rn.f32x2 %0, %1, %2, %0;" : "+l"(acc[3][2*i+1]) : "l"(ap3), "l"(bb.y));
            }
        }
        __syncthreads();
    }

    float bb8[8];
    #pragma unroll
    for (int j = 0; j < 8; j++) bb8[j] = b1l[nbase + tn + j];

    #pragma unroll
    for (int mp = 0; mp < 4; mp++) {
        #pragma unroll
        for (int h = 0; h < 2; h++) {
            size_t row = (size_t)(mbase + tm + 2 * mp + h);
            float4 o0, o1;
            float2 f0 = *(float2*)&acc[mp][0];
            float2 f1 = *(float2*)&acc[mp][1];
            float2 f2 = *(float2*)&acc[mp][2];
            float2 f3 = *(float2*)&acc[mp][3];
            float2 f4 = *(float2*)&acc[mp][4];
            float2 f5 = *(float2*)&acc[mp][5];
            float2 f6 = *(float2*)&acc[mp][6];
            float2 f7 = *(float2*)&acc[mp][7];
            o0.x = fmaxf((h ? f0.y : f0.x) + bb8[0], 0.f);
            o0.y = fmaxf((h ? f1.y : f1.x) + bb8[1], 0.f);
            o0.z = fmaxf((h ? f2.y : f2.x) + bb8[2], 0.f);
            o0.w = fmaxf((h ? f3.y : f3.x) + bb8[3], 0.f);
            o1.x = fmaxf((h ? f4.y : f4.x) + bb8[4], 0.f);
            o1.y = fmaxf((h ? f5.y : f5.x) + bb8[5], 0.f);
            o1.z = fmaxf((h ? f6.y : f6.x) + bb8[6], 0.f);
            o1.w = fmaxf((h ? f7.y : f7.x) + bb8[7], 0.f);
            *(float4*)&g_h[row * HID + nbase + tn]     = o0;
            *(float4*)&g_h[row * HID + nbase + tn + 4] = o1;
        }
    }
}

// ---------------- layer 2 mean-aggregate: warp per dst, 64 x float4 per row ----------------
__global__ void k_agg2() {
    int w    = (blockIdx.x * blockDim.x + threadIdx.x) >> 5;
    int lane = threadIdx.x & 31;
    if (w >= NN2) return;
    int beg = g_offs2[w], end = g_offs2[w + 1];

    float4 a0 = make_float4(0.f, 0.f, 0.f, 0.f);
    float4 a1 = make_float4(0.f, 0.f, 0.f, 0.f);
    for (int i = beg; i < end; i++) {
        int s = g_bucket2[i];
        const float4* r = (const float4*)(g_h + (size_t)s * HID);
        float4 v0 = r[lane];
        float4 v1 = r[lane + 32];
        a0.x += v0.x; a0.y += v0.y; a0.z += v0.z; a0.w += v0.w;
        a1.x += v1.x; a1.y += v1.y; a1.z += v1.z; a1.w += v1.w;
    }
    int cnt = end - beg;
    float inv = 1.0f / (float)(cnt > 1 ? cnt : 1);
    float4* o = (float4*)(g_agg2 + (size_t)w * HID);
    o[lane]      = make_float4(a0.x * inv, a0.y * inv, a0.z * inv, a0.w * inv);
    o[lane + 32] = make_float4(a1.x * inv, a1.y * inv, a1.z * inv, a1.w * inv);
}

// ---------------- final: out = log_softmax(agg2@W2l + b2 + h_dst@W2r) ----------------
__global__ void __launch_bounds__(256) k_final(const float* __restrict__ W2l,
                                               const float* __restrict__ b2l,
                                               const float* __restrict__ W2r,
                                               float* __restrict__ out) {
    __shared__ float abuf[8][512];
    int w    = threadIdx.x >> 5;
    int lane = threadIdx.x & 31;
    int r    = blockIdx.x * 8 + w;      // grid = 512 -> rows 0..4095

    float* a = abuf[w];
    const float* agg = g_agg2 + (size_t)r * HID;
    const float* hd  = g_h    + (size_t)r * HID;
    #pragma unroll
    for (int j = 0; j < 8; j++) {
        a[lane + 32 * j]       = agg[lane + 32 * j];
        a[256 + lane + 32 * j] = hd[lane + 32 * j];
    }
    __syncwarp();

    int o1 = lane;           // always < 47
    int o2 = lane + 32;      // valid for lanes 0..14
    bool v2 = (o2 < OUT_C);
    float acc1 = b2l[o1];
    float acc2 = v2 ? b2l[o2] : 0.f;

    #pragma unroll 4
    for (int k = 0; k < HID; k++) {
        float av = a[k];
        const float* Bk = W2l + (size_t)k * OUT_C;
        acc1 += av * Bk[o1];
        if (v2) acc2 += av * Bk[o2];
    }
    #pragma unroll 4
    for (int k = 0; k < HID; k++) {
        float av = a[256 + k];
        const float* Bk = W2r + (size_t)k * OUT_C;
        acc1 += av * Bk[o1];
        if (v2) acc2 += av * Bk[o2];
    }

    float m = v2 ? fmaxf(acc1, acc2) : acc1;
    #pragma unroll
    for (int s = 16; s; s >>= 1) m = fmaxf(m, __shfl_xor_sync(0xffffffffu, m, s));
    float e = expf(acc1 - m) + (v2 ? expf(acc2 - m) : 0.f);
    #pragma unroll
    for (int s = 16; s; s >>= 1) e += __shfl_xor_sync(0xffffffffu, e, s);
    float ls = logf(e);

    out[(size_t)r * OUT_C + o1] = acc1 - m - ls;
    if (v2) out[(size_t)r * OUT_C + o2] = acc2 - m - ls;
}

// ---------------- launch ----------------
extern "C" void kernel_launch(void* const* d_in, const int* in_sizes, int n_in,
                              void* d_out, int out_size) {
    const float* x   = (const float*)d_in[0];
    const float* W1l = (const float*)d_in[1];
    const float* b1l = (const float*)d_in[2];
    const float* W1r = (const float*)d_in[3];
    const float* W2l = (const float*)d_in[4];
    const float* b2l = (const float*)d_in[5];
    const float* W2r = (const float*)d_in[6];
    const void*  src1 = d_in[7];
    const void*  dst1 = d_in[8];
    const void*  src2 = d_in[9];
    const void*  dst2 = d_in[10];
    float* out = (float*)d_out;

    k_detect<<<1, 32>>>(src1);
    k_zero<<<(NN1 + 255) / 256, 256>>>();
    k_count<<<(EE1 + 255) / 256, 256>>>(dst1, dst2);
    k_scan<<<2, 1024>>>();
    k_scatter<<<(EE1 + 255) / 256, 256>>>(src1, dst1, src2, dst2);
    k_agg1<<<NN1 / 8, 256>>>(x);
    k_gemm1<<<dim3(HID / 128, NN1 / 128), 256>>>(x, W1l, W1r, b1l);
    k_agg2<<<NN2 / 8, 256>>>();
    k_final<<<NN2 / 8, 256>>>(W2l, b2l, W2r, out);
}

// round 3
// speedup vs baseline: 1.1820x; 1.1594x over previous
#include <cuda_runtime.h>
#include <math.h>

#define N0    1000000
#define NN1   40960
#define NN2   4096
#define EE1   1024000
#define EE2   40960
#define IN_C  100
#define HID   256
#define OUT_C 47
#define CAP1  128
#define CAP2  64

// ---------------- scratch (device globals; no allocation allowed) ----------------
__device__ int   g_is64;
__device__ int   g_cnt1[NN1];
__device__ int   g_cnt2[NN2];
__device__ int   g_bucket1[(size_t)NN1 * CAP1];
__device__ int   g_bucket2[(size_t)NN2 * CAP2];
__device__ float g_agg1[(size_t)NN1 * IN_C];
__device__ float g_h[(size_t)NN1 * HID];
__device__ float g_agg2[(size_t)NN2 * HID];

__device__ __forceinline__ int loadIdx(const void* p, int i, int is64) {
    return is64 ? (int)((const long long*)p)[i] : ((const int*)p)[i];
}

// ---------------- index dtype probe ----------------
__global__ void k_detect(const void* src1) {
    if (threadIdx.x == 0) {
        const uint2* q = (const uint2*)src1;   // if int64: .y (high word) == 0 always
        int is64 = 1;
        for (int i = 0; i < 64; i++) {
            if (q[i].y != 0u) { is64 = 0; break; }
        }
        g_is64 = is64;
    }
}

__global__ void k_zero() {
    int i = blockIdx.x * blockDim.x + threadIdx.x;
    if (i < NN1) g_cnt1[i] = 0;
    if (i < NN2) g_cnt2[i] = 0;
}

// ---------------- direct-bucket scatter (no scan, no count pass) ----------------
__global__ void k_scatter(const void* src1, const void* dst1,
                          const void* src2, const void* dst2) {
    int i = blockIdx.x * blockDim.x + threadIdx.x;
    int is64 = g_is64;
    if (i < EE1) {
        int d = loadIdx(dst1, i, is64);
        int pos = atomicAdd(&g_cnt1[d], 1);
        if (pos < CAP1) g_bucket1[(size_t)d * CAP1 + pos] = loadIdx(src1, i, is64);
    }
    if (i < EE2) {
        int d = loadIdx(dst2, i, is64);
        int pos = atomicAdd(&g_cnt2[d], 1);
        if (pos < CAP2) g_bucket2[(size_t)d * CAP2 + pos] = loadIdx(src2, i, is64);
    }
}

// ---------------- layer 1 mean-aggregate: warp per dst, 25 x float4 per row ----------------
__global__ void k_agg1(const float* __restrict__ x) {
    int w    = (blockIdx.x * blockDim.x + threadIdx.x) >> 5;
    int lane = threadIdx.x & 31;
    if (w >= NN1) return;
    int cnt = g_cnt1[w];
    if (cnt > CAP1) cnt = CAP1;
    const int* bk = g_bucket1 + (size_t)w * CAP1;

    float4 acc = make_float4(0.f, 0.f, 0.f, 0.f);
    int i = 0;
    for (; i + 1 < cnt; i += 2) {
        int s0 = bk[i], s1 = bk[i + 1];
        if (lane < 25) {
            float4 v0 = ((const float4*)(x + (size_t)s0 * IN_C))[lane];
            float4 v1 = ((const float4*)(x + (size_t)s1 * IN_C))[lane];
            acc.x += v0.x + v1.x; acc.y += v0.y + v1.y;
            acc.z += v0.z + v1.z; acc.w += v0.w + v1.w;
        }
    }
    if (i < cnt) {
        int s0 = bk[i];
        if (lane < 25) {
            float4 v0 = ((const float4*)(x + (size_t)s0 * IN_C))[lane];
            acc.x += v0.x; acc.y += v0.y; acc.z += v0.z; acc.w += v0.w;
        }
    }
    float inv = 1.0f / (float)(cnt > 1 ? cnt : 1);
    if (lane < 25) {
        float4 o = make_float4(acc.x * inv, acc.y * inv, acc.z * inv, acc.w * inv);
        ((float4*)(g_agg1 + (size_t)w * IN_C))[lane] = o;
    }
}

// ---------------- GEMM1 fused: h = relu([agg1 | x_dst] @ [W1l; W1r] + b1) ----------------
// M=40960, K=200 (virtual concat), N=256. BM=BN=128, BK=8, 256 threads.
// Packed f32x2 FMA; B duplicated {b,b} in chunk-swizzled smem.
__global__ void __launch_bounds__(256) k_gemm1(const float* __restrict__ x,
                                               const float* __restrict__ W1l,
                                               const float* __restrict__ W1r,
                                               const float* __restrict__ b1l) {
    __shared__ float As[8][128];     // [k][m]
    __shared__ float BsD[8 * 256];   // duplicated B, chunk-swizzled

    int tid = threadIdx.x;
    int g   = tid & 15;              // n-group 0..15
    int tm  = (tid >> 4) * 8;        // 0..120
    int tn  = g * 8;                 // 0..120
    int mbase = blockIdx.y * 128;
    int nbase = blockIdx.x * 128;

    unsigned long long acc[4][8];
    #pragma unroll
    for (int mp = 0; mp < 4; mp++)
        #pragma unroll
        for (int n = 0; n < 8; n++) acc[mp][n] = 0ULL;

    int a_row  = tid >> 1;           // 0..127
    int a_col4 = (tid & 1) * 4;      // 0 or 4
    int b_k    = tid >> 5;           // 0..7
    int b_n4   = (tid & 31) * 4;     // 0..124
    int bg     = b_n4 >> 3;          // group 0..15
    int bi0    = (b_n4 & 7) >> 1;    // chunk 0 or 2

    for (int t = 0; t < 25; t++) {   // K=200 = 25*8
        int k0 = t * 8;
        {
            int m_g = mbase + a_row;
            int kc  = k0 + a_col4;
            const float* src = (kc < IN_C)
                ? (g_agg1 + (size_t)m_g * IN_C + kc)
                : (x + (size_t)m_g * IN_C + (kc - IN_C));
            float4 v = *(const float4*)src;
            As[a_col4 + 0][a_row] = v.x;
            As[a_col4 + 1][a_row] = v.y;
            As[a_col4 + 2][a_row] = v.z;
            As[a_col4 + 3][a_row] = v.w;
        }
        {
            int kg = k0 + b_k;
            const float* src = (kg < IN_C)
                ? (W1l + (size_t)kg * HID + nbase + b_n4)
                : (W1r + (size_t)(kg - IN_C) * HID + nbase + b_n4);
            float4 v = *(const float4*)src;
            float4 c0 = make_float4(v.x, v.x, v.y, v.y);
            float4 c1 = make_float4(v.z, v.z, v.w, v.w);
            *(float4*)&BsD[b_k * 256 + ((bi0    ) * 16 + bg) * 4] = c0;
            *(float4*)&BsD[b_k * 256 + ((bi0 + 1) * 16 + bg) * 4] = c1;
        }
        __syncthreads();

        #pragma unroll
        for (int kk = 0; kk < 8; kk++) {
            ulonglong2 a0 = *(const ulonglong2*)&As[kk][tm];
            ulonglong2 a1 = *(const ulonglong2*)&As[kk][tm + 4];
            unsigned long long ap0 = a0.x, ap1 = a0.y, ap2 = a1.x, ap3 = a1.y;
            #pragma unroll
            for (int i = 0; i < 4; i++) {
                ulonglong2 bb = *(const ulonglong2*)&BsD[kk * 256 + (i * 16 + g) * 4];
                asm("fma.rn.f32x2 %0, %1, %2, %0;" : "+l"(acc[0][2*i  ]) : "l"(ap0), "l"(bb.x));
                asm("fma.rn.f32x2 %0, %1, %2, %0;" : "+l"(acc[1][2*i  ]) : "l"(ap1), "l"(bb.x));
                asm("fma.rn.f32x2 %0, %1, %2, %0;" : "+l"(acc[2][2*i  ]) : "l"(ap2), "l"(bb.x));
                asm("fma.rn.f32x2 %0, %1, %2, %0;" : "+l"(acc[3][2*i  ]) : "l"(ap3), "l"(bb.x));
                asm("fma.rn.f32x2 %0, %1, %2, %0;" : "+l"(acc[0][2*i+1]) : "l"(ap0), "l"(bb.y));
                asm("fma.rn.f32x2 %0, %1, %2, %0;" : "+l"(acc[1][2*i+1]) : "l"(ap1), "l"(bb.y));
                asm("fma.rn.f32x2 %0, %1, %2, %0;" : "+l"(acc[2][2*i+1]) : "l"(ap2), "l"(bb.y));
                asm("fma.rn.f32x2 %0, %1, %2, %0;" : "+l"(acc[3][2*i+1]) : "l"(ap3), "l"(bb.y));
            }
        }
        __syncthreads();
    }

    float bb8[8];
    #pragma unroll
    for (int j = 0; j < 8; j++) bb8[j] = b1l[nbase + tn + j];

    #pragma unroll
    for (int mp = 0; mp < 4; mp++) {
        #pragma unroll
        for (int h = 0; h < 2; h++) {
            size_t row = (size_t)(mbase + tm + 2 * mp + h);
            float4 o0, o1;
            float2 f0 = *(float2*)&acc[mp][0];
            float2 f1 = *(float2*)&acc[mp][1];
            float2 f2 = *(float2*)&acc[mp][2];
            float2 f3 = *(float2*)&acc[mp][3];
            float2 f4 = *(float2*)&acc[mp][4];
            float2 f5 = *(float2*)&acc[mp][5];
            float2 f6 = *(float2*)&acc[mp][6];
            float2 f7 = *(float2*)&acc[mp][7];
            o0.x = fmaxf((h ? f0.y : f0.x) + bb8[0], 0.f);
            o0.y = fmaxf((h ? f1.y : f1.x) + bb8[1], 0.f);
            o0.z = fmaxf((h ? f2.y : f2.x) + bb8[2], 0.f);
            o0.w = fmaxf((h ? f3.y : f3.x) + bb8[3], 0.f);
            o1.x = fmaxf((h ? f4.y : f4.x) + bb8[4], 0.f);
            o1.y = fmaxf((h ? f5.y : f5.x) + bb8[5], 0.f);
            o1.z = fmaxf((h ? f6.y : f6.x) + bb8[6], 0.f);
            o1.w = fmaxf((h ? f7.y : f7.x) + bb8[7], 0.f);
            *(float4*)&g_h[row * HID + nbase + tn]     = o0;
            *(float4*)&g_h[row * HID + nbase + tn + 4] = o1;
        }
    }
}

// ---------------- layer 2 mean-aggregate: warp per dst, 64 x float4 per row ----------------
__global__ void k_agg2() {
    int w    = (blockIdx.x * blockDim.x + threadIdx.x) >> 5;
    int lane = threadIdx.x & 31;
    if (w >= NN2) return;
    int cnt = g_cnt2[w];
    if (cnt > CAP2) cnt = CAP2;
    const int* bk = g_bucket2 + (size_t)w * CAP2;

    float4 a0 = make_float4(0.f, 0.f, 0.f, 0.f);
    float4 a1 = make_float4(0.f, 0.f, 0.f, 0.f);
    for (int i = 0; i < cnt; i++) {
        int s = bk[i];
        const float4* r = (const float4*)(g_h + (size_t)s * HID);
        float4 v0 = r[lane];
        float4 v1 = r[lane + 32];
        a0.x += v0.x; a0.y += v0.y; a0.z += v0.z; a0.w += v0.w;
        a1.x += v1.x; a1.y += v1.y; a1.z += v1.z; a1.w += v1.w;
    }
    float inv = 1.0f / (float)(cnt > 1 ? cnt : 1);
    float4* o = (float4*)(g_agg2 + (size_t)w * HID);
    o[lane]      = make_float4(a0.x * inv, a0.y * inv, a0.z * inv, a0.w * inv);
    o[lane + 32] = make_float4(a1.x * inv, a1.y * inv, a1.z * inv, a1.w * inv);
}

// ---------------- final: out = log_softmax(agg2@W2l + b2 + h_dst@W2r) ----------------
__global__ void __launch_bounds__(256) k_final(const float* __restrict__ W2l,
                                               const float* __restrict__ b2l,
                                               const float* __restrict__ W2r,
                                               float* __restrict__ out) {
    __shared__ float abuf[8][512];
    int w    = threadIdx.x >> 5;
    int lane = threadIdx.x & 31;
    int r    = blockIdx.x * 8 + w;      // grid = 512 -> rows 0..4095

    float* a = abuf[w];
    const float* agg = g_agg2 + (size_t)r * HID;
    const float* hd  = g_h    + (size_t)r * HID;
    #pragma unroll
    for (int j = 0; j < 8; j++) {
        a[lane + 32 * j]       = agg[lane + 32 * j];
        a[256 + lane + 32 * j] = hd[lane + 32 * j];
    }
    __syncwarp();

    int o1 = lane;           // always < 47
    int o2 = lane + 32;      // valid for lanes 0..14
    bool v2 = (o2 < OUT_C);
    float acc1 = b2l[o1];
    float acc2 = v2 ? b2l[o2] : 0.f;

    #pragma unroll 4
    for (int k = 0; k < HID; k++) {
        float av = a[k];
        const float* Bk = W2l + (size_t)k * OUT_C;
        acc1 += av * Bk[o1];
        if (v2) acc2 += av * Bk[o2];
    }
    #pragma unroll 4
    for (int k = 0; k < HID; k++) {
        float av = a[256 + k];
        const float* Bk = W2r + (size_t)k * OUT_C;
        acc1 += av * Bk[o1];
        if (v2) acc2 += av * Bk[o2];
    }

    float m = v2 ? fmaxf(acc1, acc2) : acc1;
    #pragma unroll
    for (int s = 16; s; s >>= 1) m = fmaxf(m, __shfl_xor_sync(0xffffffffu, m, s));
    float e = expf(acc1 - m) + (v2 ? expf(acc2 - m) : 0.f);
    #pragma unroll
    for (int s = 16; s; s >>= 1) e += __shfl_xor_sync(0xffffffffu, e, s);
    float ls = logf(e);

    out[(size_t)r * OUT_C + o1] = acc1 - m - ls;
    if (v2) out[(size_t)r * OUT_C + o2] = acc2 - m - ls;
}

// ---------------- launch ----------------
extern "C" void kernel_launch(void* const* d_in, const int* in_sizes, int n_in,
                              void* d_out, int out_size) {
    const float* x   = (const float*)d_in[0];
    const float* W1l = (const float*)d_in[1];
    const float* b1l = (const float*)d_in[2];
    const float* W1r = (const float*)d_in[3];
    const float* W2l = (const float*)d_in[4];
    const float* b2l = (const float*)d_in[5];
    const float* W2r = (const float*)d_in[6];
    const void*  src1 = d_in[7];
    const void*  dst1 = d_in[8];
    const void*  src2 = d_in[9];
    const void*  dst2 = d_in[10];
    float* out = (float*)d_out;

    k_detect<<<1, 32>>>(src1);
    k_zero<<<(NN1 + 255) / 256, 256>>>();
    k_scatter<<<(EE1 + 255) / 256, 256>>>(src1, dst1, src2, dst2);
    k_agg1<<<NN1 / 8, 256>>>(x);
    k_gemm1<<<dim3(HID / 128, NN1 / 128), 256>>>(x, W1l, W1r, b1l);
    k_agg2<<<NN2 / 8, 256>>>();
    k_final<<<NN2 / 8, 256>>>(W2l, b2l, W2r, out);
}

// round 4
// speedup vs baseline: 1.3424x; 1.1357x over previous
#include <cuda_runtime.h>
#include <math.h>

#define N0    1000000
#define NN1   40960
#define NN2   4096
#define EE1   1024000
#define EE2   40960
#define IN_C  100
#define HID   256
#define OUT_C 47
#define CAP1  128
#define CAP2  64

// ---------------- scratch (device globals; no allocation allowed) ----------------
__device__ int   g_is64;
__device__ int   g_cnt1[NN1];
__device__ int   g_cnt2[NN2];
__device__ int   g_bucket1[(size_t)NN1 * CAP1];
__device__ int   g_bucket2[(size_t)NN2 * CAP2];
__device__ float g_agg1[(size_t)NN1 * IN_C];
__device__ float g_h[(size_t)NN1 * HID];
__device__ float g_agg2[(size_t)NN2 * HID];

__device__ __forceinline__ int loadIdx(const void* p, int i, int is64) {
    return is64 ? (int)((const long long*)p)[i] : ((const int*)p)[i];
}

// ---------------- init: zero counters + index dtype probe (merged) ----------------
__global__ void k_init(const void* src1) {
    int i = blockIdx.x * blockDim.x + threadIdx.x;
    if (i < NN1) g_cnt1[i] = 0;
    if (i < NN2) g_cnt2[i] = 0;
    if (i == 0) {
        const uint2* q = (const uint2*)src1;   // if int64: high words all zero
        int is64 = 1;
        for (int k = 0; k < 64; k++) {
            if (q[k].y != 0u) { is64 = 0; break; }
        }
        g_is64 = is64;
    }
}

// ---------------- direct-bucket scatter (no scan, no count pass) ----------------
__global__ void k_scatter(const void* src1, const void* dst1,
                          const void* src2, const void* dst2) {
    int i = blockIdx.x * blockDim.x + threadIdx.x;
    int is64 = g_is64;
    if (i < EE1) {
        int d = loadIdx(dst1, i, is64);
        int pos = atomicAdd(&g_cnt1[d], 1);
        if (pos < CAP1) g_bucket1[(size_t)d * CAP1 + pos] = loadIdx(src1, i, is64);
    }
    if (i < EE2) {
        int d = loadIdx(dst2, i, is64);
        int pos = atomicAdd(&g_cnt2[d], 1);
        if (pos < CAP2) g_bucket2[(size_t)d * CAP2 + pos] = loadIdx(src2, i, is64);
    }
}

// ---------------- layer 1 mean-aggregate: warp per dst, 25 x float4 per row ----------------
__global__ void k_agg1(const float* __restrict__ x) {
    int w    = (blockIdx.x * blockDim.x + threadIdx.x) >> 5;
    int lane = threadIdx.x & 31;
    if (w >= NN1) return;
    int cnt = g_cnt1[w];
    if (cnt > CAP1) cnt = CAP1;
    const int* bk = g_bucket1 + (size_t)w * CAP1;

    float4 acc = make_float4(0.f, 0.f, 0.f, 0.f);
    int i = 0;
    for (; i + 3 < cnt; i += 4) {
        int s0 = bk[i], s1 = bk[i + 1], s2 = bk[i + 2], s3 = bk[i + 3];
        if (lane < 25) {
            float4 v0 = ((const float4*)(x + (size_t)s0 * IN_C))[lane];
            float4 v1 = ((const float4*)(x + (size_t)s1 * IN_C))[lane];
            float4 v2 = ((const float4*)(x + (size_t)s2 * IN_C))[lane];
            float4 v3 = ((const float4*)(x + (size_t)s3 * IN_C))[lane];
            acc.x += (v0.x + v1.x) + (v2.x + v3.x);
            acc.y += (v0.y + v1.y) + (v2.y + v3.y);
            acc.z += (v0.z + v1.z) + (v2.z + v3.z);
            acc.w += (v0.w + v1.w) + (v2.w + v3.w);
        }
    }
    for (; i < cnt; i++) {
        int s0 = bk[i];
        if (lane < 25) {
            float4 v0 = ((const float4*)(x + (size_t)s0 * IN_C))[lane];
            acc.x += v0.x; acc.y += v0.y; acc.z += v0.z; acc.w += v0.w;
        }
    }
    float inv = 1.0f / (float)(cnt > 1 ? cnt : 1);
    if (lane < 25) {
        float4 o = make_float4(acc.x * inv, acc.y * inv, acc.z * inv, acc.w * inv);
        ((float4*)(g_agg1 + (size_t)w * IN_C))[lane] = o;
    }
}

// ---------------- GEMM1 fused: h = relu([agg1 | x_dst] @ [W1l; W1r] + b1) ----------------
// M=40960, K=200 (virtual concat), N=256. BM=128, BN=128, 128 threads.
// Per-thread 16m x 8n: 8 m-pairs (f32x2 packed over m) x 8 n.
// A smem natural [k][m] (pairs contiguous); B smem duplicated {b,b} stored in
// the exact chunk order the inner loop reads -> inner B loads are 2-address
// broadcasts (conflict-free).
__global__ void __launch_bounds__(128) k_gemm1(const float* __restrict__ x,
                                               const float* __restrict__ W1l,
                                               const float* __restrict__ W1r,
                                               const float* __restrict__ b1l) {
    __shared__ float As[8][128];     // [k][m]
    __shared__ float BsD[8 * 256];   // [k][dup-pair chunks], chunk c=(i*16+g) -> n {32i+2g, +1}

    int tid = threadIdx.x;
    int g   = tid & 15;              // n-group 0..15
    int bk  = tid >> 4;              // 0..7 (B k-row loader; also m-block)
    int tm  = bk * 16;               // m base 0..112
    int mbase = blockIdx.y * 128;
    int nbase = blockIdx.x * 128;

    unsigned long long acc[8][8];
    #pragma unroll
    for (int mp = 0; mp < 8; mp++)
        #pragma unroll
        for (int n = 0; n < 8; n++) acc[mp][n] = 0ULL;

    for (int t = 0; t < 25; t++) {   // K=200 = 25*8
        int k0 = t * 8;
        // A: row mbase+tid, cols k0..k0+7 (virtual concat agg1|x), store transposed
        {
            int m_g = mbase + tid;
            #pragma unroll
            for (int half = 0; half < 2; half++) {
                int kc = k0 + half * 4;
                const float* src = (kc < IN_C)
                    ? (g_agg1 + (size_t)m_g * IN_C + kc)
                    : (x + (size_t)m_g * IN_C + (kc - IN_C));
                float4 v = *(const float4*)src;
                As[half * 4 + 0][tid] = v.x;
                As[half * 4 + 1][tid] = v.y;
                As[half * 4 + 2][tid] = v.z;
                As[half * 4 + 3][tid] = v.w;
            }
        }
        // B: k-row kg = k0+bk, thread g loads n = 32i+2g (+1), duplicates
        {
            int kg = k0 + bk;
            const float* wrow = (kg < IN_C)
                ? (W1l + (size_t)kg * HID)
                : (W1r + (size_t)(kg - IN_C) * HID);
            #pragma unroll
            for (int i = 0; i < 4; i++) {
                float2 v = *(const float2*)&wrow[nbase + 32 * i + 2 * g];
                float4 d = make_float4(v.x, v.x, v.y, v.y);
                *(float4*)&BsD[bk * 256 + (i * 16 + g) * 4] = d;
            }
        }
        __syncthreads();

        #pragma unroll
        for (int kk = 0; kk < 8; kk++) {
            ulonglong2 A0 = *(const ulonglong2*)&As[kk][tm];
            ulonglong2 A1 = *(const ulonglong2*)&As[kk][tm + 4];
            ulonglong2 A2 = *(const ulonglong2*)&As[kk][tm + 8];
            ulonglong2 A3 = *(const ulonglong2*)&As[kk][tm + 12];
            unsigned long long ap0 = A0.x, ap1 = A0.y, ap2 = A1.x, ap3 = A1.y;
            unsigned long long ap4 = A2.x, ap5 = A2.y, ap6 = A3.x, ap7 = A3.y;
            #pragma unroll
            for (int i = 0; i < 4; i++) {
                ulonglong2 bb = *(const ulonglong2*)&BsD[kk * 256 + (i * 16 + g) * 4];
                asm("fma.rn.f32x2 %0, %1, %2, %0;" : "+l"(acc[0][2*i  ]) : "l"(ap0), "l"(bb.x));
                asm("fma.rn.f32x2 %0, %1, %2, %0;" : "+l"(acc[1][2*i  ]) : "l"(ap1), "l"(bb.x));
                asm("fma.rn.f32x2 %0, %1, %2, %0;" : "+l"(acc[2][2*i  ]) : "l"(ap2), "l"(bb.x));
                asm("fma.rn.f32x2 %0, %1, %2, %0;" : "+l"(acc[3][2*i  ]) : "l"(ap3), "l"(bb.x));
                asm("fma.rn.f32x2 %0, %1, %2, %0;" : "+l"(acc[4][2*i  ]) : "l"(ap4), "l"(bb.x));
                asm("fma.rn.f32x2 %0, %1, %2, %0;" : "+l"(acc[5][2*i  ]) : "l"(ap5), "l"(bb.x));
                asm("fma.rn.f32x2 %0, %1, %2, %0;" : "+l"(acc[6][2*i  ]) : "l"(ap6), "l"(bb.x));
                asm("fma.rn.f32x2 %0, %1, %2, %0;" : "+l"(acc[7][2*i  ]) : "l"(ap7), "l"(bb.x));
                asm("fma.rn.f32x2 %0, %1, %2, %0;" : "+l"(acc[0][2*i+1]) : "l"(ap0), "l"(bb.y));
                asm("fma.rn.f32x2 %0, %1, %2, %0;" : "+l"(acc[1][2*i+1]) : "l"(ap1), "l"(bb.y));
                asm("fma.rn.f32x2 %0, %1, %2, %0;" : "+l"(acc[2][2*i+1]) : "l"(ap2), "l"(bb.y));
                asm("fma.rn.f32x2 %0, %1, %2, %0;" : "+l"(acc[3][2*i+1]) : "l"(ap3), "l"(bb.y));
                asm("fma.rn.f32x2 %0, %1, %2, %0;" : "+l"(acc[4][2*i+1]) : "l"(ap4), "l"(bb.y));
                asm("fma.rn.f32x2 %0, %1, %2, %0;" : "+l"(acc[5][2*i+1]) : "l"(ap5), "l"(bb.y));
                asm("fma.rn.f32x2 %0, %1, %2, %0;" : "+l"(acc[6][2*i+1]) : "l"(ap6), "l"(bb.y));
                asm("fma.rn.f32x2 %0, %1, %2, %0;" : "+l"(acc[7][2*i+1]) : "l"(ap7), "l"(bb.y));
            }
        }
        __syncthreads();
    }

    // epilogue: bias + relu, write 16 rows x 8 cols (cols n = 32i+2g, +1)
    float2 bias[4];
    #pragma unroll
    for (int i = 0; i < 4; i++)
        bias[i] = *(const float2*)&b1l[nbase + 32 * i + 2 * g];

    #pragma unroll
    for (int mp = 0; mp < 8; mp++) {
        #pragma unroll
        for (int h = 0; h < 2; h++) {
            size_t row = (size_t)(mbase + tm + 2 * mp + h);
            #pragma unroll
            for (int i = 0; i < 4; i++) {
                float2 p0 = *(float2*)&acc[mp][2 * i];
                float2 p1 = *(float2*)&acc[mp][2 * i + 1];
                float v0 = (h ? p0.y : p0.x) + bias[i].x;
                float v1 = (h ? p1.y : p1.x) + bias[i].y;
                float2 o = make_float2(fmaxf(v0, 0.f), fmaxf(v1, 0.f));
                *(float2*)&g_h[row * HID + nbase + 32 * i + 2 * g] = o;
            }
        }
    }
}

// ---------------- layer 2 mean-aggregate: warp per dst, 64 x float4 per row ----------------
__global__ void k_agg2() {
    int w    = (blockIdx.x * blockDim.x + threadIdx.x) >> 5;
    int lane = threadIdx.x & 31;
    if (w >= NN2) return;
    int cnt = g_cnt2[w];
    if (cnt > CAP2) cnt = CAP2;
    const int* bk = g_bucket2 + (size_t)w * CAP2;

    float4 a0 = make_float4(0.f, 0.f, 0.f, 0.f);
    float4 a1 = make_float4(0.f, 0.f, 0.f, 0.f);
    for (int i = 0; i < cnt; i++) {
        int s = bk[i];
        const float4* r = (const float4*)(g_h + (size_t)s * HID);
        float4 v0 = r[lane];
        float4 v1 = r[lane + 32];
        a0.x += v0.x; a0.y += v0.y; a0.z += v0.z; a0.w += v0.w;
        a1.x += v1.x; a1.y += v1.y; a1.z += v1.z; a1.w += v1.w;
    }
    float inv = 1.0f / (float)(cnt > 1 ? cnt : 1);
    float4* o = (float4*)(g_agg2 + (size_t)w * HID);
    o[lane]      = make_float4(a0.x * inv, a0.y * inv, a0.z * inv, a0.w * inv);
    o[lane + 32] = make_float4(a1.x * inv, a1.y * inv, a1.z * inv, a1.w * inv);
}

// ---------------- final: out = log_softmax(agg2@W2l + b2 + h_dst@W2r) ----------------
__global__ void __launch_bounds__(256) k_final(const float* __restrict__ W2l,
                                               const float* __restrict__ b2l,
                                               const float* __restrict__ W2r,
                                               float* __restrict__ out) {
    __shared__ float abuf[8][512];
    int w    = threadIdx.x >> 5;
    int lane = threadIdx.x & 31;
    int r    = blockIdx.x * 8 + w;      // grid = 512 -> rows 0..4095

    float* a = abuf[w];
    const float* agg = g_agg2 + (size_t)r * HID;
    const float* hd  = g_h    + (size_t)r * HID;
    #pragma unroll
    for (int j = 0; j < 8; j++) {
        a[lane + 32 * j]       = agg[lane + 32 * j];
        a[256 + lane + 32 * j] = hd[lane + 32 * j];
    }
    __syncwarp();

    int o1 = lane;           // always < 47
    int o2 = lane + 32;      // valid for lanes 0..14
    bool v2 = (o2 < OUT_C);
    float acc1 = b2l[o1];
    float acc2 = v2 ? b2l[o2] : 0.f;

    #pragma unroll 4
    for (int k = 0; k < HID; k++) {
        float av = a[k];
        const float* Bk = W2l + (size_t)k * OUT_C;
        acc1 += av * Bk[o1];
        if (v2) acc2 += av * Bk[o2];
    }
    #pragma unroll 4
    for (int k = 0; k < HID; k++) {
        float av = a[256 + k];
        const float* Bk = W2r + (size_t)k * OUT_C;
        acc1 += av * Bk[o1];
        if (v2) acc2 += av * Bk[o2];
    }

    float m = v2 ? fmaxf(acc1, acc2) : acc1;
    #pragma unroll
    for (int s = 16; s; s >>= 1) m = fmaxf(m, __shfl_xor_sync(0xffffffffu, m, s));
    float e = expf(acc1 - m) + (v2 ? expf(acc2 - m) : 0.f);
    #pragma unroll
    for (int s = 16; s; s >>= 1) e += __shfl_xor_sync(0xffffffffu, e, s);
    float ls = logf(e);

    out[(size_t)r * OUT_C + o1] = acc1 - m - ls;
    if (v2) out[(size_t)r * OUT_C + o2] = acc2 - m - ls;
}

// ---------------- launch ----------------
extern "C" void kernel_launch(void* const* d_in, const int* in_sizes, int n_in,
                              void* d_out, int out_size) {
    const float* x   = (const float*)d_in[0];
    const float* W1l = (const float*)d_in[1];
    const float* b1l = (const float*)d_in[2];
    const float* W1r = (const float*)d_in[3];
    const float* W2l = (const float*)d_in[4];
    const float* b2l = (const float*)d_in[5];
    const float* W2r = (const float*)d_in[6];
    const void*  src1 = d_in[7];
    const void*  dst1 = d_in[8];
    const void*  src2 = d_in[9];
    const void*  dst2 = d_in[10];
    float* out = (float*)d_out;

    k_init<<<(NN1 + 255) / 256, 256>>>(src1);
    k_scatter<<<(EE1 + 255) / 256, 256>>>(src1, dst1, src2, dst2);
    k_agg1<<<NN1 / 8, 256>>>(x);
    k_gemm1<<<dim3(HID / 128, NN1 / 128), 128>>>(x, W1l, W1r, b1l);
    k_agg2<<<NN2 / 8, 256>>>();
    k_final<<<NN2 / 8, 256>>>(W2l, b2l, W2r, out);
}

// round 7
// speedup vs baseline: 1.5268x; 1.1374x over previous
#include <cuda_runtime.h>
#include <cuda_bf16.h>
#include <math.h>
#include <stdint.h>

#define N0    1000000
#define NN1   40960
#define NN2   4096
#define EE1   1024000
#define EE2   40960
#define IN_C  100
#define HID   256
#define OUT_C 47
#define CAP1  128
#define CAP2  64
#define KPAD  208          // 13 * 16

// ---------------- scratch (device globals; no allocation allowed) ----------------
__device__ int   g_is64;
__device__ int   g_cnt1[NN1];
__device__ int   g_cnt2[NN2];
__device__ int   g_bucket1[(size_t)NN1 * CAP1];
__device__ int   g_bucket2[(size_t)NN2 * CAP2];
__device__ float g_agg1[(size_t)NN1 * IN_C];
__device__ float g_h[(size_t)NN1 * HID];
__device__ float g_agg2[(size_t)NN2 * HID];
__device__ __align__(16) __nv_bfloat16 g_Bhi[(size_t)KPAD * HID];  // [k][n]
__device__ __align__(16) __nv_bfloat16 g_Blo[(size_t)KPAD * HID];

__device__ __forceinline__ int loadIdx(const void* p, int i, int is64) {
    return is64 ? (int)((const long long*)p)[i] : ((const int*)p)[i];
}
__device__ __forceinline__ uint32_t smem_u32(const void* p) {
    uint32_t a;
    asm("{ .reg .u64 t; cvta.to.shared.u64 t, %1; cvt.u32.u64 %0, t; }" : "=r"(a) : "l"(p));
    return a;
}
__device__ __forceinline__ uint32_t pack_bf2(__nv_bfloat16 a, __nv_bfloat16 b) {
    return (uint32_t)__bfloat16_as_ushort(a) | ((uint32_t)__bfloat16_as_ushort(b) << 16);
}

#define LDMX4(r0, r1, r2, r3, a) \
    asm volatile("ldmatrix.sync.aligned.m8n8.x4.shared.b16 {%0,%1,%2,%3}, [%4];" \
        : "=r"(r0), "=r"(r1), "=r"(r2), "=r"(r3) : "r"(a))
#define LDMX4T(r0, r1, r2, r3, a) \
    asm volatile("ldmatrix.sync.aligned.m8n8.x4.trans.shared.b16 {%0,%1,%2,%3}, [%4];" \
        : "=r"(r0), "=r"(r1), "=r"(r2), "=r"(r3) : "r"(a))

__device__ __forceinline__ void mma16816(float* c, const uint32_t* a, uint32_t b0, uint32_t b1) {
    asm volatile("mma.sync.aligned.m16n8k16.row.col.f32.bf16.bf16.f32 "
        "{%0,%1,%2,%3}, {%4,%5,%6,%7}, {%8,%9}, {%0,%1,%2,%3};"
        : "+f"(c[0]), "+f"(c[1]), "+f"(c[2]), "+f"(c[3])
        : "r"(a[0]), "r"(a[1]), "r"(a[2]), "r"(a[3]), "r"(b0), "r"(b1));
}

// ---------------- init: zero counters + index dtype probe ----------------
__global__ void k_init(const void* src1) {
    int i = blockIdx.x * blockDim.x + threadIdx.x;
    if (i < NN1) g_cnt1[i] = 0;
    if (i < NN2) g_cnt2[i] = 0;
    if (i == 0) {
        const uint2* q = (const uint2*)src1;
        int is64 = 1;
        for (int k = 0; k < 64; k++) {
            if (q[k].y != 0u) { is64 = 0; break; }
        }
        g_is64 = is64;
    }
}

// ---------------- direct-bucket scatter ----------------
__global__ void k_scatter(const void* src1, const void* dst1,
                          const void* src2, const void* dst2) {
    int i = blockIdx.x * blockDim.x + threadIdx.x;
    int is64 = g_is64;
    if (i < EE1) {
        int d = loadIdx(dst1, i, is64);
        int pos = atomicAdd(&g_cnt1[d], 1);
        if (pos < CAP1) g_bucket1[(size_t)d * CAP1 + pos] = loadIdx(src1, i, is64);
    }
    if (i < EE2) {
        int d = loadIdx(dst2, i, is64);
        int pos = atomicAdd(&g_cnt2[d], 1);
        if (pos < CAP2) g_bucket2[(size_t)d * CAP2 + pos] = loadIdx(src2, i, is64);
    }
}

// ---------------- B hi/lo split build: [KPAD][HID] bf16, k-major ----------------
__global__ void k_prepB(const float* __restrict__ W1l, const float* __restrict__ W1r) {
    int idx = blockIdx.x * blockDim.x + threadIdx.x;
    if (idx >= KPAD * HID) return;
    int k = idx / HID, n = idx % HID;
    float w = 0.f;
    if (k < IN_C)            w = W1l[(size_t)k * HID + n];
    else if (k < 2 * IN_C)   w = W1r[(size_t)(k - IN_C) * HID + n];
    __nv_bfloat16 hi = __float2bfloat16(w);
    g_Bhi[idx] = hi;
    g_Blo[idx] = __float2bfloat16(w - __bfloat162float(hi));
}

// ---------------- layer 1 mean-aggregate ----------------
__global__ void k_agg1(const float* __restrict__ x) {
    int w    = (blockIdx.x * blockDim.x + threadIdx.x) >> 5;
    int lane = threadIdx.x & 31;
    if (w >= NN1) return;
    int cnt = g_cnt1[w];
    if (cnt > CAP1) cnt = CAP1;
    const int* bk = g_bucket1 + (size_t)w * CAP1;

    float4 acc = make_float4(0.f, 0.f, 0.f, 0.f);
    int i = 0;
    for (; i + 3 < cnt; i += 4) {
        int s0 = bk[i], s1 = bk[i + 1], s2 = bk[i + 2], s3 = bk[i + 3];
        if (lane < 25) {
            float4 v0 = ((const float4*)(x + (size_t)s0 * IN_C))[lane];
            float4 v1 = ((const float4*)(x + (size_t)s1 * IN_C))[lane];
            float4 v2 = ((const float4*)(x + (size_t)s2 * IN_C))[lane];
            float4 v3 = ((const float4*)(x + (size_t)s3 * IN_C))[lane];
            acc.x += (v0.x + v1.x) + (v2.x + v3.x);
            acc.y += (v0.y + v1.y) + (v2.y + v3.y);
            acc.z += (v0.z + v1.z) + (v2.z + v3.z);
            acc.w += (v0.w + v1.w) + (v2.w + v3.w);
        }
    }
    for (; i < cnt; i++) {
        int s0 = bk[i];
        if (lane < 25) {
            float4 v0 = ((const float4*)(x + (size_t)s0 * IN_C))[lane];
            acc.x += v0.x; acc.y += v0.y; acc.z += v0.z; acc.w += v0.w;
        }
    }
    float inv = 1.0f / (float)(cnt > 1 ? cnt : 1);
    if (lane < 25) {
        float4 o = make_float4(acc.x * inv, acc.y * inv, acc.z * inv, acc.w * inv);
        ((float4*)(g_agg1 + (size_t)w * IN_C))[lane] = o;
    }
}

// ---------------- GEMM1 via mma.sync bf16 3-term split ----------------
// h = relu([agg1|x] @ [W1l;W1r] + b1).  M=40960, N=256(BN=128), K=200->208.
// 256 threads = 8 warps (4 m x 2 n), warp tile 32x64, BK=16.
#define ASTRIDE 24     // bf16 elems per A smem row (16 + 8 pad), 48B
#define BSTRIDE 136    // bf16 elems per B smem row (128 + 8 pad), 272B
__global__ void __launch_bounds__(256) k_gemm1_mma(const float* __restrict__ x,
                                                   const float* __restrict__ b1l) {
    __shared__ __nv_bfloat16 Ahi[128 * ASTRIDE];
    __shared__ __nv_bfloat16 Alo[128 * ASTRIDE];
    __shared__ __nv_bfloat16 Bhi[16 * BSTRIDE];
    __shared__ __nv_bfloat16 Blo[16 * BSTRIDE];

    int tid  = threadIdx.x;
    int wid  = tid >> 5, lane = tid & 31;
    int wm   = wid & 3;            // warp m index (32 rows each)
    int wn   = wid >> 2;           // warp n index (64 cols each)
    int mbase = blockIdx.y * 128;
    int nbase = blockIdx.x * 128;

    float acc[2][8][4];
    #pragma unroll
    for (int a = 0; a < 2; a++)
        #pragma unroll
        for (int b = 0; b < 8; b++)
            #pragma unroll
            for (int c = 0; c < 4; c++) acc[a][b][c] = 0.f;

    // A loader mapping: thread -> row = tid/2, cols (tid&1)*8 .. +7
    int a_row  = tid >> 1;
    int a_c0   = (tid & 1) * 8;
    const float* aggrow = g_agg1 + (size_t)(mbase + a_row) * IN_C;
    const float* xrow   = x + (size_t)(mbase + a_row) * IN_C;

    // B loader mapping: thread -> k = tid/16, col8 = (tid&15)*8
    int b_k   = tid >> 4;
    int b_c   = (tid & 15) * 8;

    // ldmatrix source addresses (iter-invariant)
    uint32_t ahi_b = smem_u32(Ahi), alo_b = smem_u32(Alo);
    uint32_t bhi_b = smem_u32(Bhi), blo_b = smem_u32(Blo);
    // A: per m-block mb: row = wm*32 + mb*16 + lane%16, byte col = (lane/16)*16
    uint32_t a_off[2];
    #pragma unroll
    for (int mb = 0; mb < 2; mb++)
        a_off[mb] = (uint32_t)((wm * 32 + mb * 16 + (lane & 15)) * (ASTRIDE * 2) + (lane >> 4) * 16);
    // B: per n16-group gq: k = lane%16, col = wn*64 + gq*16 + (lane/16)*8
    uint32_t b_off[4];
    #pragma unroll
    for (int gq = 0; gq < 4; gq++)
        b_off[gq] = (uint32_t)((lane & 15) * (BSTRIDE * 2) + (wn * 64 + gq * 16 + (lane >> 4) * 8) * 2);

    for (int t = 0; t < 13; t++) {
        int k0 = t * 16;
        // ---- stage A: fp32 -> bf16 hi/lo ----
        #pragma unroll
        for (int j = 0; j < 2; j++) {
            int kc = k0 + a_c0 + j * 4;
            float4 v = make_float4(0.f, 0.f, 0.f, 0.f);
            if (kc < 2 * IN_C)
                v = *(const float4*)((kc < IN_C) ? (aggrow + kc) : (xrow + kc - IN_C));
            __nv_bfloat16 h0 = __float2bfloat16(v.x), h1 = __float2bfloat16(v.y);
            __nv_bfloat16 h2 = __float2bfloat16(v.z), h3 = __float2bfloat16(v.w);
            __nv_bfloat16 l0 = __float2bfloat16(v.x - __bfloat162float(h0));
            __nv_bfloat16 l1 = __float2bfloat16(v.y - __bfloat162float(h1));
            __nv_bfloat16 l2 = __float2bfloat16(v.z - __bfloat162float(h2));
            __nv_bfloat16 l3 = __float2bfloat16(v.w - __bfloat162float(h3));
            int so = a_row * ASTRIDE + a_c0 + j * 4;
            *(uint2*)&Ahi[so] = make_uint2(pack_bf2(h0, h1), pack_bf2(h2, h3));
            *(uint2*)&Alo[so] = make_uint2(pack_bf2(l0, l1), pack_bf2(l2, l3));
        }
        // ---- stage B: copy prebuilt hi/lo rows ----
        {
            size_t go = (size_t)(k0 + b_k) * HID + nbase + b_c;
            int so = b_k * BSTRIDE + b_c;
            *(uint4*)&Bhi[so] = *(const uint4*)&g_Bhi[go];
            *(uint4*)&Blo[so] = *(const uint4*)&g_Blo[go];
        }
        __syncthreads();

        // ---- fragments ----
        uint32_t ah[2][4], al[2][4], bf[4][4];
        #pragma unroll
        for (int mb = 0; mb < 2; mb++) {
            LDMX4(ah[mb][0], ah[mb][1], ah[mb][2], ah[mb][3], ahi_b + a_off[mb]);
            LDMX4(al[mb][0], al[mb][1], al[mb][2], al[mb][3], alo_b + a_off[mb]);
        }
        // B_hi: hh + lh
        #pragma unroll
        for (int gq = 0; gq < 4; gq++)
            LDMX4T(bf[gq][0], bf[gq][1], bf[gq][2], bf[gq][3], bhi_b + b_off[gq]);
        #pragma unroll
        for (int mb = 0; mb < 2; mb++)
            #pragma unroll
            for (int gq = 0; gq < 4; gq++) {
                mma16816(acc[mb][gq * 2 + 0], ah[mb], bf[gq][0], bf[gq][1]);
                mma16816(acc[mb][gq * 2 + 1], ah[mb], bf[gq][2], bf[gq][3]);
                mma16816(acc[mb][gq * 2 + 0], al[mb], bf[gq][0], bf[gq][1]);
                mma16816(acc[mb][gq * 2 + 1], al[mb], bf[gq][2], bf[gq][3]);
            }
        // B_lo: hl
        #pragma unroll
        for (int gq = 0; gq < 4; gq++)
            LDMX4T(bf[gq][0], bf[gq][1], bf[gq][2], bf[gq][3], blo_b + b_off[gq]);
        #pragma unroll
        for (int mb = 0; mb < 2; mb++)
            #pragma unroll
            for (int gq = 0; gq < 4; gq++) {
                mma16816(acc[mb][gq * 2 + 0], ah[mb], bf[gq][0], bf[gq][1]);
                mma16816(acc[mb][gq * 2 + 1], ah[mb], bf[gq][2], bf[gq][3]);
            }
        __syncthreads();
    }

    // ---- epilogue: bias + relu ----
    #pragma unroll
    for (int mb = 0; mb < 2; mb++) {
        int row0 = mbase + wm * 32 + mb * 16 + (lane >> 2);
        #pragma unroll
        for (int nb = 0; nb < 8; nb++) {
            int col = nbase + wn * 64 + nb * 8 + (lane & 3) * 2;
            float2 bias = *(const float2*)&b1l[col];
            float2 o0, o1;
            o0.x = fmaxf(acc[mb][nb][0] + bias.x, 0.f);
            o0.y = fmaxf(acc[mb][nb][1] + bias.y, 0.f);
            o1.x = fmaxf(acc[mb][nb][2] + bias.x, 0.f);
            o1.y = fmaxf(acc[mb][nb][3] + bias.y, 0.f);
            *(float2*)&g_h[(size_t)row0 * HID + col]       = o0;
            *(float2*)&g_h[(size_t)(row0 + 8) * HID + col] = o1;
        }
    }
}

// ---------------- layer 2 mean-aggregate ----------------
__global__ void k_agg2() {
    int w    = (blockIdx.x * blockDim.x + threadIdx.x) >> 5;
    int lane = threadIdx.x & 31;
    if (w >= NN2) return;
    int cnt = g_cnt2[w];
    if (cnt > CAP2) cnt = CAP2;
    const int* bk = g_bucket2 + (size_t)w * CAP2;

    float4 a0 = make_float4(0.f, 0.f, 0.f, 0.f);
    float4 a1 = make_float4(0.f, 0.f, 0.f, 0.f);
    for (int i = 0; i < cnt; i++) {
        int s = bk[i];
        const float4* r = (const float4*)(g_h + (size_t)s * HID);
        float4 v0 = r[lane];
        float4 v1 = r[lane + 32];
        a0.x += v0.x; a0.y += v0.y; a0.z += v0.z; a0.w += v0.w;
        a1.x += v1.x; a1.y += v1.y; a1.z += v1.z; a1.w += v1.w;
    }
    float inv = 1.0f / (float)(cnt > 1 ? cnt : 1);
    float4* o = (float4*)(g_agg2 + (size_t)w * HID);
    o[lane]      = make_float4(a0.x * inv, a0.y * inv, a0.z * inv, a0.w * inv);
    o[lane + 32] = make_float4(a1.x * inv, a1.y * inv, a1.z * inv, a1.w * inv);
}

// ---------------- final: out = log_softmax(agg2@W2l + b2 + h_dst@W2r) ----------------
__global__ void __launch_bounds__(256) k_final(const float* __restrict__ W2l,
                                               const float* __restrict__ b2l,
                                               const float* __restrict__ W2r,
                                               float* __restrict__ out) {
    __shared__ float abuf[8][512];
    int w    = threadIdx.x >> 5;
    int lane = threadIdx.x & 31;
    int r    = blockIdx.x * 8 + w;

    float* a = abuf[w];
    const float* agg = g_agg2 + (size_t)r * HID;
    const float* hd  = g_h    + (size_t)r * HID;
    #pragma unroll
    for (int j = 0; j < 8; j++) {
        a[lane + 32 * j]       = agg[lane + 32 * j];
        a[256 + lane + 32 * j] = hd[lane + 32 * j];
    }
    __syncwarp();

    int o1 = lane;
    int o2 = lane + 32;
    bool v2 = (o2 < OUT_C);
    float acc1 = b2l[o1];
    float acc2 = v2 ? b2l[o2] : 0.f;

    #pragma unroll 4
    for (int k = 0; k < HID; k++) {
        float av = a[k];
        const float* Bk = W2l + (size_t)k * OUT_C;
        acc1 += av * Bk[o1];
        if (v2) acc2 += av * Bk[o2];
    }
    #pragma unroll 4
    for (int k = 0; k < HID; k++) {
        float av = a[256 + k];
        const float* Bk = W2r + (size_t)k * OUT_C;
        acc1 += av * Bk[o1];
        if (v2) acc2 += av * Bk[o2];
    }

    float m = v2 ? fmaxf(acc1, acc2) : acc1;
    #pragma unroll
    for (int s = 16; s; s >>= 1) m = fmaxf(m, __shfl_xor_sync(0xffffffffu, m, s));
    float e = expf(acc1 - m) + (v2 ? expf(acc2 - m) : 0.f);
    #pragma unroll
    for (int s = 16; s; s >>= 1) e += __shfl_xor_sync(0xffffffffu, e, s);
    float ls = logf(e);

    out[(size_t)r * OUT_C + o1] = acc1 - m - ls;
    if (v2) out[(size_t)r * OUT_C + o2] = acc2 - m - ls;
}

// ---------------- launch ----------------
extern "C" void kernel_launch(void* const* d_in, const int* in_sizes, int n_in,
                              void* d_out, int out_size) {
    const float* x   = (const float*)d_in[0];
    const float* W1l = (const float*)d_in[1];
    const float* b1l = (const float*)d_in[2];
    const float* W1r = (const float*)d_in[3];
    const float* W2l = (const float*)d_in[4];
    const float* b2l = (const float*)d_in[5];
    const float* W2r = (const float*)d_in[6];
    const void*  src1 = d_in[7];
    const void*  dst1 = d_in[8];
    const void*  src2 = d_in[9];
    const void*  dst2 = d_in[10];
    float* out = (float*)d_out;

    k_init<<<(NN1 + 255) / 256, 256>>>(src1);
    k_prepB<<<(KPAD * HID + 255) / 256, 256>>>(W1l, W1r);
    k_scatter<<<(EE1 + 255) / 256, 256>>>(src1, dst1, src2, dst2);
    k_agg1<<<NN1 / 8, 256>>>(x);
    k_gemm1_mma<<<dim3(2, NN1 / 128), 256>>>(x, b1l);
    k_agg2<<<NN2 / 8, 256>>>();
    k_final<<<NN2 / 8, 256>>>(W2l, b2l, W2r, out);
}